// round 7
// baseline (speedup 1.0000x reference)
#include <cuda_runtime.h>
#include <cuda_bf16.h>
#include <math_constants.h>

// VectorQuantizer, D=1, N=512, x: [8,16,64,64] fp32 — single fused kernel, v3.
// 512 blocks x 512 threads (4 blocks/SM -> ~100% occ). Each block:
//   - bitonic-sorts the 512 codes (double-buffered smem steps, shfl intra-warp)
//   - builds an Eytzinger (BFS) pivot tree -> near-conflict-free 9-level search
//   - quantizes one (b,h) slice of 1024 elems, padded-smem transpose
//     replicating the reference's view([B,H,W,C]).permute bug
//   - fused loss partial; last block finalizes both loss scalars.

#define BQ 8
#define CQ 16
#define HQ 64
#define WQ 64
#define NCODE 512
#define NELEM (BQ*CQ*HQ*WQ)       // 524288
#define NBLK  (BQ*HQ)             // 512 blocks, one (b,h) slice each
#define NT    512

__device__ float g_partial[NBLK];
__device__ unsigned int g_count = 0;

__global__ __launch_bounds__(NT)
void vq_fused_kernel(const float* __restrict__ x, const float* __restrict__ w,
                     float* __restrict__ out, int nq) {
    __shared__ float sbuf[2][NCODE];        // sort ping-pong; final = sorted
    __shared__ float s_eyt[NCODE];          // BFS pivot tree, idx 1..511
    __shared__ float s_tile[WQ * 17];       // padded transpose tile
    __shared__ float s_warp[16];
    __shared__ int   s_last;

    const int tid = threadIdx.x;
    const int slice = blockIdx.x;           // = b*64 + h
    const int base = slice * 1024;

    // ---- issue x loads early (2-way MLP) while sorting ----
    float v0 = x[base + tid];
    float v1 = x[base + NT + tid];

    // ---- bitonic sort, 512 threads, double-buffered smem (1 sync/step) ----
    float sv = w[tid];
    int pb = 0;
    for (int k = 2; k <= NCODE; k <<= 1) {
        int j = k >> 1;
        for (; j >= 32; j >>= 1) {          // cross-warp exchange via smem
            sbuf[pb][tid] = sv;
            __syncthreads();
            float o = sbuf[pb][tid ^ j];
            bool keepMin = (((tid & j) == 0) == ((tid & k) == 0));
            sv = keepMin ? fminf(sv, o) : fmaxf(sv, o);
            pb ^= 1;
        }
#pragma unroll
        for (; j >= 1; j >>= 1) {           // intra-warp exchange via shfl
            float o = __shfl_xor_sync(0xffffffffu, sv, j);
            bool keepMin = (((tid & j) == 0) == ((tid & k) == 0));
            sv = keepMin ? fminf(sv, o) : fmaxf(sv, o);
        }
    }
    sbuf[pb][tid] = sv;                     // sorted ascending
    __syncthreads();

    // ---- build Eytzinger pivot tree: node t (1..511), depth d, offset p ----
    if (tid >= 1) {
        int d = 31 - __clz(tid);
        int p = tid - (1 << d);
        int idx = (((2 * p + 1) << (8 - d)) - 1);
        s_eyt[tid] = sbuf[pb][idx];
    }
    __syncthreads();

    // ---- 9-level tree search for both elements (interleaved for MLP) ----
    int k0 = 1, k1 = 1;
#pragma unroll
    for (int l = 0; l < 9; l++) {
        k0 = 2 * k0 + (s_eyt[k0] <= v0 ? 1 : 0);
        k1 = 2 * k1 + (s_eyt[k1] <= v1 ? 1 : 0);
    }
    int pos0 = k0 - NCODE;                  // == lower-bound pos in [0,511]
    int pos1 = k1 - NCODE;

    const float* __restrict__ srt = sbuf[pb];
    float q0, q1;
    if (pos0 == 0) q0 = srt[0];
    else {
        float lo = srt[pos0 - 1], hi = srt[pos0];
        q0 = ((v0 - lo) <= (hi - v0)) ? lo : hi;
    }
    if (pos1 == 0) q1 = srt[0];
    else {
        float lo = srt[pos1 - 1], hi = srt[pos1];
        q1 = ((v1 - lo) <= (hi - v1)) ? lo : hi;
    }

    // ---- stage into transpose tile: local j -> (w = j>>4, c = j&15) ----
    s_tile[(tid >> 4) * 17 + (tid & 15)] = q0;
    {
        int j1 = tid + NT;
        s_tile[(j1 >> 4) * 17 + (j1 & 15)] = q1;
    }
    __syncthreads();

    // ---- transposed read, output write, fused loss ----
    const int b = slice >> 6, h = slice & 63;
    const int obase = b * (CQ * HQ * WQ) + h * WQ;
    float acc = 0.f;
#pragma unroll
    for (int e = 0; e < 2; e++) {
        int t2 = tid + e * NT;
        int c2 = t2 >> 6, w2 = t2 & 63;
        float q = s_tile[w2 * 17 + c2];
        int i = obase + c2 * (HQ * WQ) + w2;
        float xv = x[i];
        out[i] = xv + (q - xv);             // straight-through, literal
        float d = xv - q;
        acc += d * d;
    }

    // ---- block reduce (fixed order -> deterministic) ----
#pragma unroll
    for (int o = 16; o; o >>= 1) acc += __shfl_down_sync(0xffffffffu, acc, o);
    if ((tid & 31) == 0) s_warp[tid >> 5] = acc;
    __syncthreads();
    if (tid < 32) {
        float a = (tid < 16) ? s_warp[tid] : 0.f;
#pragma unroll
        for (int o = 8; o; o >>= 1) a += __shfl_down_sync(0xffffffffu, a, o);
        if (tid == 0) {
            g_partial[blockIdx.x] = a;
            __threadfence();
            unsigned int prev = atomicAdd(&g_count, 1u);
            s_last = (prev == (unsigned)(NBLK - 1)) ? 1 : 0;
        }
    }
    __syncthreads();

    // ---- last block finalizes losses (deterministic order) ----
    if (s_last) {
        __threadfence();
        float a = g_partial[tid];
#pragma unroll
        for (int o = 16; o; o >>= 1) a += __shfl_down_sync(0xffffffffu, a, o);
        if ((tid & 31) == 0) s_warp[tid >> 5] = a;
        __syncthreads();
        if (tid == 0) {
            float total = 0.f;
#pragma unroll
            for (int i = 0; i < 16; i++) total += s_warp[i];
            float mean = total / (float)NELEM;
            out[nq]     = mean;             // q_latent_loss
            out[nq + 1] = mean;             // e_latent_loss
            g_count = 0;                    // reset for next graph replay
        }
    }
}

extern "C" void kernel_launch(void* const* d_in, const int* in_sizes, int n_in,
                              void* d_out, int out_size) {
    const float* x = (const float*)d_in[0];
    const float* w = (const float*)d_in[1];
    float* out = (float*)d_out;
    int nq = out_size - 2;
    vq_fused_kernel<<<NBLK, NT>>>(x, w, out, nq);
}

// round 8
// speedup vs baseline: 1.2402x; 1.2402x over previous
#include <cuda_runtime.h>
#include <cuda_bf16.h>
#include <math_constants.h>

// VectorQuantizer, D=1, N=512, x: [8,16,64,64] fp32.
// K1 (1 block): hybrid bitonic sort of 512 codes -> Eytzinger tree in gmem
//               (eyt[0] holds sorted[511]; nodes 1..511 are BFS pivots).
// K2 (512 blocks x 512 thr): 9-level tree descent with lo/hi tracking (no
//               sorted array needed), padded-smem transpose replicating the
//               reference view([B,H,W,C]).permute bug, fused loss; last block
//               finalizes both loss scalars.

#define BQ 8
#define CQ 16
#define HQ 64
#define WQ 64
#define NCODE 512
#define NELEM (BQ*CQ*HQ*WQ)       // 524288
#define NBLK  (BQ*HQ)             // 512
#define NT    512

__device__ float g_eyt[NCODE];          // [0]=sorted[511], [1..511]=BFS pivots
__device__ float g_partial[NBLK];
__device__ unsigned int g_count = 0;

// ---------------- Kernel 1: sort + Eytzinger build ----------------
__global__ __launch_bounds__(NCODE) void vq_sort_kernel(const float* __restrict__ w) {
    __shared__ float sbuf[2][NCODE];
    const int tid = threadIdx.x;
    float sv = w[tid];
    int pb = 0;
    for (int k = 2; k <= NCODE; k <<= 1) {
        int j = k >> 1;
        for (; j >= 32; j >>= 1) {          // cross-warp via smem ping-pong
            sbuf[pb][tid] = sv;
            __syncthreads();
            float o = sbuf[pb][tid ^ j];
            bool keepMin = (((tid & j) == 0) == ((tid & k) == 0));
            sv = keepMin ? fminf(sv, o) : fmaxf(sv, o);
            pb ^= 1;
        }
#pragma unroll
        for (; j >= 1; j >>= 1) {           // intra-warp via shfl
            float o = __shfl_xor_sync(0xffffffffu, sv, j);
            bool keepMin = (((tid & j) == 0) == ((tid & k) == 0));
            sv = keepMin ? fminf(sv, o) : fmaxf(sv, o);
        }
    }
    // rank of sv == tid. Map sorted index -> Eytzinger node.
    // idx+1 = (2p+1)<<tz ; d = 8-tz ; node = (1<<d)+p ; idx=511 -> slot 0.
    int v = tid + 1;
    int tz = __ffs(v) - 1;
    int node;
    if (tz >= 9) node = 0;                  // sorted[511]
    else {
        int d = 8 - tz;
        int p = ((v >> tz) - 1) >> 1;
        node = (1 << d) + p;
    }
    g_eyt[node] = sv;
}

// ---------------- Kernel 2: quantize + permute + loss ----------------
__global__ __launch_bounds__(NT)
void vq_main_kernel(const float* __restrict__ x, float* __restrict__ out, int nq) {
    __shared__ float s_eyt[NCODE];
    __shared__ float s_tile[WQ * 17];       // padded transpose tile
    __shared__ float s_warp[16];
    __shared__ int   s_last;

    const int tid = threadIdx.x;
    const int slice = blockIdx.x;           // = b*64 + h
    const float maxcode = g_eyt[0];         // sorted[511] (L2-broadcast)

    // early float2 gather: elements j0=2*tid, j1=2*tid+1 of this slice
    float2 vv = *(const float2*)(x + slice * 1024 + 2 * tid);

    s_eyt[tid] = g_eyt[tid];
    __syncthreads();

    // ---- 9-level descent with lo/hi neighbor tracking ----
    float lo0 = -CUDART_INF_F, hi0 = maxcode;
    float lo1 = -CUDART_INF_F, hi1 = maxcode;
    int k0 = 1, k1 = 1;
#pragma unroll
    for (int l = 0; l < 9; l++) {
        float p0 = s_eyt[k0], p1 = s_eyt[k1];
        bool r0 = (p0 <= vv.x), r1 = (p1 <= vv.y);
        lo0 = r0 ? p0 : lo0;  hi0 = r0 ? hi0 : p0;
        lo1 = r1 ? p1 : lo1;  hi1 = r1 ? hi1 : p1;
        k0 = 2 * k0 + (r0 ? 1 : 0);
        k1 = 2 * k1 + (r1 ? 1 : 0);
    }
    float q0 = ((vv.x - lo0) <= (hi0 - vv.x)) ? lo0 : hi0;
    float q1 = ((vv.y - lo1) <= (hi1 - vv.y)) ? lo1 : hi1;

    // ---- stage into transpose tile: local j -> (w=j>>4, c=j&15) ----
    {
        int j0 = 2 * tid, j1 = 2 * tid + 1;
        s_tile[(j0 >> 4) * 17 + (j0 & 15)] = q0;
        s_tile[(j1 >> 4) * 17 + (j1 & 15)] = q1;
    }
    __syncthreads();

    // ---- transposed read, float2 write, fused loss ----
    const int b = slice >> 6, h = slice & 63;
    const int t2 = 2 * tid;
    const int c2 = t2 >> 6, w2 = t2 & 63;   // w2 even -> pair in same row
    float qa = s_tile[w2 * 17 + c2];
    float qb = s_tile[(w2 + 1) * 17 + c2];
    int i = b * (CQ * HQ * WQ) + c2 * (HQ * WQ) + h * WQ + w2;
    float2 xv = *(const float2*)(x + i);
    float2 ov;
    ov.x = xv.x + (qa - xv.x);              // straight-through, literal
    ov.y = xv.y + (qb - xv.y);
    *(float2*)(out + i) = ov;
    float d0 = xv.x - qa, d1 = xv.y - qb;
    float acc = d0 * d0 + d1 * d1;

    // ---- block reduce (fixed order -> deterministic) ----
#pragma unroll
    for (int o = 16; o; o >>= 1) acc += __shfl_down_sync(0xffffffffu, acc, o);
    if ((tid & 31) == 0) s_warp[tid >> 5] = acc;
    __syncthreads();
    if (tid < 32) {
        float a = (tid < 16) ? s_warp[tid] : 0.f;
#pragma unroll
        for (int o = 8; o; o >>= 1) a += __shfl_down_sync(0xffffffffu, a, o);
        if (tid == 0) {
            g_partial[blockIdx.x] = a;
            __threadfence();
            unsigned int prev = atomicAdd(&g_count, 1u);
            s_last = (prev == (unsigned)(NBLK - 1)) ? 1 : 0;
        }
    }
    __syncthreads();

    // ---- last block finalizes losses (deterministic order) ----
    if (s_last) {
        __threadfence();
        float a = g_partial[tid];
#pragma unroll
        for (int o = 16; o; o >>= 1) a += __shfl_down_sync(0xffffffffu, a, o);
        if ((tid & 31) == 0) s_warp[tid >> 5] = a;
        __syncthreads();
        if (tid == 0) {
            float total = 0.f;
#pragma unroll
            for (int i2 = 0; i2 < 16; i2++) total += s_warp[i2];
            float mean = total / (float)NELEM;
            out[nq]     = mean;             // q_latent_loss
            out[nq + 1] = mean;             // e_latent_loss
            g_count = 0;                    // reset for next graph replay
        }
    }
}

extern "C" void kernel_launch(void* const* d_in, const int* in_sizes, int n_in,
                              void* d_out, int out_size) {
    const float* x = (const float*)d_in[0];
    const float* w = (const float*)d_in[1];
    float* out = (float*)d_out;
    int nq = out_size - 2;
    vq_sort_kernel<<<1, NCODE>>>(w);
    vq_main_kernel<<<NBLK, NT>>>(x, out, nq);
}